// round 2
// baseline (speedup 1.0000x reference)
#include <cuda_runtime.h>
#include <cuda_bf16.h>

#define N_NODES 50000
#define N_EDGES 800000
#define D_IN    128
#define D_OUT   64

// Scratch for h = x @ W  (50000 x 64 fp32 = 12.8 MB; fits in L2 for the scatter phase)
__device__ float g_h[N_NODES * D_OUT];

// ---------------------------------------------------------------------------
// Kernel 1: h = x @ W   (50000x128 @ 128x64)
// Block: 256 threads = 16 rows x 16 col-groups (4 cols each, float4 accum).
// W (32KB) and a 16x128 x-tile (8KB) staged in shared memory.
// ---------------------------------------------------------------------------
__global__ __launch_bounds__(256) void gemm_kernel(
    const float* __restrict__ x,
    const float* __restrict__ w,
    float* __restrict__ h)
{
    __shared__ float Ws[D_IN][D_OUT];   // 32 KB
    __shared__ float Xs[16][D_IN];      // 8 KB

    const int t = threadIdx.x;

    // Load W: 8192 floats = 2048 float4, 8 per thread
    {
        const float4* w4 = (const float4*)w;
        float4* ws4 = (float4*)&Ws[0][0];
        #pragma unroll
        for (int i = 0; i < 8; i++) ws4[t + i * 256] = w4[t + i * 256];
    }
    // Load x tile: 16 rows x 128 = 2048 floats = 512 float4, 2 per thread
    {
        const int row0 = blockIdx.x * 16;
        const float4* x4 = (const float4*)(x + (size_t)row0 * D_IN);
        float4* xs4 = (float4*)&Xs[0][0];
        xs4[t]       = x4[t];
        xs4[t + 256] = x4[t + 256];
    }
    __syncthreads();

    const int r = t >> 4;   // row within tile, 0..15
    const int g = t & 15;   // col-group, 0..15 (4 cols each)

    float4 acc = make_float4(0.f, 0.f, 0.f, 0.f);
    #pragma unroll
    for (int k = 0; k < D_IN; k++) {
        const float  xv = Xs[r][k];
        const float4 wv = *(const float4*)&Ws[k][g * 4];
        acc.x = fmaf(xv, wv.x, acc.x);
        acc.y = fmaf(xv, wv.y, acc.y);
        acc.z = fmaf(xv, wv.z, acc.z);
        acc.w = fmaf(xv, wv.w, acc.w);
    }

    const int row = blockIdx.x * 16 + r;
    *(float4*)&h[(size_t)row * D_OUT + g * 4] = acc;
}

// ---------------------------------------------------------------------------
// Kernel 2: out[i][c] = bias[c]   (out is poisoned by the harness)
// ---------------------------------------------------------------------------
__global__ __launch_bounds__(256) void init_kernel(
    float* __restrict__ out,
    const float* __restrict__ bias)
{
    __shared__ float bs[D_OUT];
    if (threadIdx.x < D_OUT) bs[threadIdx.x] = bias[threadIdx.x];
    __syncthreads();
    const int i = blockIdx.x * blockDim.x + threadIdx.x;
    if (i < N_NODES * D_OUT) out[i] = bs[i & (D_OUT - 1)];
}

// ---------------------------------------------------------------------------
// Kernel 3: scatter-add over edges.
// edge_dst is SORTED, so runs of equal dst are contiguous -> accumulate runs
// in registers, one atomicAdd per run per chunk (atomics only at run/chunk
// boundaries; ~16 edges per node on average).
// Block: 64 threads, thread t owns output dim t (coalesced 256B per edge).
// Software prefetch of the next edge's h value hides the ~250cyc L2 latency.
// ---------------------------------------------------------------------------
#define EDGES_PER_BLOCK 128

__global__ __launch_bounds__(64) void scatter_kernel(
    const int*   __restrict__ src,
    const int*   __restrict__ dst,
    const float* __restrict__ vals,
    const float* __restrict__ h,
    float*       __restrict__ out)
{
    const int t = threadIdx.x;                 // dim 0..63
    const int e_begin = blockIdx.x * EDGES_PER_BLOCK;
    int e_end = e_begin + EDGES_PER_BLOCK;
    if (e_end > N_EDGES) e_end = N_EDGES;
    if (e_begin >= e_end) return;

    // prefetch edge e_begin
    int   d0 = __ldg(&dst[e_begin]);
    float v0 = __ldg(&vals[e_begin]);
    float h0 = __ldg(&h[(size_t)__ldg(&src[e_begin]) * D_OUT + t]);

    int   cur = d0;
    float acc = 0.f;

    for (int e = e_begin; e < e_end; e++) {
        // prefetch edge e+1 while we consume edge e
        int   d1 = 0;
        float v1 = 0.f, h1 = 0.f;
        if (e + 1 < e_end) {
            d1 = __ldg(&dst[e + 1]);
            v1 = __ldg(&vals[e + 1]);
            h1 = __ldg(&h[(size_t)__ldg(&src[e + 1]) * D_OUT + t]);
        }

        if (d0 != cur) {                       // run boundary -> flush
            atomicAdd(&out[(size_t)cur * D_OUT + t], acc);
            acc = 0.f;
            cur = d0;
        }
        acc = fmaf(v0, h0, acc);

        d0 = d1; v0 = v1; h0 = h1;
    }
    atomicAdd(&out[(size_t)cur * D_OUT + t], acc);
}

// ---------------------------------------------------------------------------
// Launch
// Inputs (metadata order): x, edge_src, edge_dst, edge_vals, weight, bias
// ---------------------------------------------------------------------------
extern "C" void kernel_launch(void* const* d_in, const int* in_sizes, int n_in,
                              void* d_out, int out_size)
{
    const float* x        = (const float*)d_in[0];
    const int*   edge_src = (const int*)  d_in[1];
    const int*   edge_dst = (const int*)  d_in[2];
    const float* edge_val = (const float*)d_in[3];
    const float* weight   = (const float*)d_in[4];
    const float* bias     = (const float*)d_in[5];
    float*       out      = (float*)d_out;

    float* h;
    cudaGetSymbolAddress((void**)&h, g_h);

    // 1) h = x @ W
    gemm_kernel<<<N_NODES / 16, 256>>>(x, weight, h);

    // 2) out = bias (broadcast)
    init_kernel<<<(N_NODES * D_OUT + 255) / 256, 256>>>(out, bias);

    // 3) out[dst] += val * h[src]
    const int nblk = (N_EDGES + EDGES_PER_BLOCK - 1) / EDGES_PER_BLOCK;
    scatter_kernel<<<nblk, 64>>>(edge_src, edge_dst, edge_val, h, out);
}

// round 5
// speedup vs baseline: 1.8537x; 1.8537x over previous
#include <cuda_runtime.h>
#include <cuda_bf16.h>

#define N_NODES 50000
#define N_EDGES 800000
#define D_IN    128
#define D_OUT   64

// Scratch for h = x @ W (12.8 MB fp32; L2-resident during scatter)
__device__ float g_h[N_NODES * D_OUT];

// ---------------------------------------------------------------------------
// Kernel 1: h = x @ W   (50000x128 @ 128x64)
// 128 threads/block, tile = 64 rows x 64 cols (full D_OUT).
// Thread (rg, cg): 4 rows x 8 cols register blocking.
// Xs padded to 132 floats/row: 528 B = 33*16 -> float4 stores ALIGNED.
// (133 was conflict-optimal but misaligned -> HW trap. 132 gives a benign
//  2-way LDS conflict on x reads; loop is issue-bound anyway.)
// ---------------------------------------------------------------------------
__global__ __launch_bounds__(128) void gemm_kernel(
    const float* __restrict__ x,
    const float* __restrict__ w,
    float* __restrict__ h)
{
    __shared__ __align__(16) float Xs[64][132];     // 33 KB, 16B-aligned rows
    __shared__ __align__(16) float Ws[D_IN][D_OUT]; // 32 KB

    const int t = threadIdx.x;
    const int row0 = blockIdx.x * 64;

    // Load W: 2048 float4, 16 per thread
    {
        const float4* w4 = (const float4*)w;
        #pragma unroll
        for (int i = 0; i < 16; i++) {
            const int idx = t + i * 128;          // float4 index into [128][16]
            const int rr = idx >> 4, cc = idx & 15;
            *(float4*)&Ws[rr][cc * 4] = w4[idx];
        }
    }
    // Load x tile: 64 rows x 128 = 2048 float4, 16 per thread (rows clamped)
    {
        #pragma unroll
        for (int i = 0; i < 16; i++) {
            const int idx = t + i * 128;          // float4 index into [64][32]
            const int rr = idx >> 5, cc = idx & 31;
            int grow = row0 + rr;
            if (grow > N_NODES - 1) grow = N_NODES - 1;
            *(float4*)&Xs[rr][cc * 4] = *(const float4*)&x[(size_t)grow * D_IN + cc * 4];
        }
    }
    __syncthreads();

    const int rg = t >> 3;     // 0..15 -> rows rg*4 .. rg*4+3
    const int cg = t & 7;      // 0..7  -> cols cg*8 .. cg*8+7

    float4 a0[4], a1[4];
    #pragma unroll
    for (int i = 0; i < 4; i++) {
        a0[i] = make_float4(0.f, 0.f, 0.f, 0.f);
        a1[i] = make_float4(0.f, 0.f, 0.f, 0.f);
    }

    #pragma unroll 8
    for (int k = 0; k < D_IN; k++) {
        const float4 w0 = *(const float4*)&Ws[k][cg * 8];
        const float4 w1 = *(const float4*)&Ws[k][cg * 8 + 4];
        #pragma unroll
        for (int i = 0; i < 4; i++) {
            const float xv = Xs[rg * 4 + i][k];
            a0[i].x = fmaf(xv, w0.x, a0[i].x);
            a0[i].y = fmaf(xv, w0.y, a0[i].y);
            a0[i].z = fmaf(xv, w0.z, a0[i].z);
            a0[i].w = fmaf(xv, w0.w, a0[i].w);
            a1[i].x = fmaf(xv, w1.x, a1[i].x);
            a1[i].y = fmaf(xv, w1.y, a1[i].y);
            a1[i].z = fmaf(xv, w1.z, a1[i].z);
            a1[i].w = fmaf(xv, w1.w, a1[i].w);
        }
    }

    #pragma unroll
    for (int i = 0; i < 4; i++) {
        const int grow = row0 + rg * 4 + i;
        if (grow < N_NODES) {
            *(float4*)&h[(size_t)grow * D_OUT + cg * 8]     = a0[i];
            *(float4*)&h[(size_t)grow * D_OUT + cg * 8 + 4] = a1[i];
        }
    }
}

// ---------------------------------------------------------------------------
// Kernel 2: out[i][c] = bias[c]  (float4 broadcast; d_out is poisoned)
// ---------------------------------------------------------------------------
__global__ __launch_bounds__(256) void init_kernel(
    float* __restrict__ out,
    const float* __restrict__ bias)
{
    __shared__ float4 bs4[16];
    if (threadIdx.x < 16) bs4[threadIdx.x] = ((const float4*)bias)[threadIdx.x];
    __syncthreads();
    const int i = blockIdx.x * blockDim.x + threadIdx.x;   // float4 index
    if (i < N_NODES * D_OUT / 4) ((float4*)out)[i] = bs4[i & 15];
}

// ---------------------------------------------------------------------------
// Kernel 3: scatter-add.  128 threads = 8 subgroups of 16 lanes.
// Lane l owns dims [4l..4l+3] (float4; one edge = 16 lanes x 16B = 256B).
// 512 edges/block staged into smem once; each subgroup runs 64 edges with
// sorted-dst run-length accumulation + depth-1 prefetch of next h row.
// ---------------------------------------------------------------------------
#define EPB 512

__device__ __forceinline__ void flush_acc(float* out, int node, int lane, float4 a)
{
    float* p = &out[(size_t)node * D_OUT + lane * 4];
    atomicAdd(p + 0, a.x);
    atomicAdd(p + 1, a.y);
    atomicAdd(p + 2, a.z);
    atomicAdd(p + 3, a.w);
}

__global__ __launch_bounds__(128) void scatter_kernel(
    const int*   __restrict__ src,
    const int*   __restrict__ dst,
    const float* __restrict__ vals,
    const float* __restrict__ h,
    float*       __restrict__ out)
{
    __shared__ __align__(16) int   s_src[EPB];
    __shared__ __align__(16) int   s_dst[EPB];
    __shared__ __align__(16) float s_val[EPB];

    const int t = threadIdx.x;
    const int e0 = blockIdx.x * EPB;
    int n = N_EDGES - e0;
    if (n > EPB) n = EPB;

    // Stage edge data (vec4 where in-bounds; e0 is 512-aligned so vec-aligned)
    {
        const int i = t;                 // 128 threads x 4 edges = 512
        const int e = e0 + i * 4;
        if (e + 3 < N_EDGES) {
            *(int4*)  &s_src[i * 4] = *(const int4*)  &src[e];
            *(int4*)  &s_dst[i * 4] = *(const int4*)  &dst[e];
            *(float4*)&s_val[i * 4] = *(const float4*)&vals[e];
        } else {
            #pragma unroll
            for (int j = 0; j < 4; j++) {
                if (e + j < N_EDGES) {
                    s_src[i * 4 + j] = src[e + j];
                    s_dst[i * 4 + j] = dst[e + j];
                    s_val[i * 4 + j] = vals[e + j];
                }
            }
        }
    }
    __syncthreads();

    const int sg   = t >> 4;     // subgroup 0..7
    const int lane = t & 15;     // dim group: float4 at 4*lane
    const int lo = sg * (EPB / 8);
    int hi = lo + (EPB / 8);
    if (hi > n) hi = n;
    if (lo >= hi) return;

    // Prefetch first edge
    int    d0 = s_dst[lo];
    float  v0 = s_val[lo];
    float4 h0 = *(const float4*)&h[(size_t)s_src[lo] * D_OUT + lane * 4];

    int cur = d0;
    float4 acc = make_float4(0.f, 0.f, 0.f, 0.f);

    for (int i = lo; i < hi - 1; i++) {
        // prefetch edge i+1 (unconditional in main loop)
        const int    d1 = s_dst[i + 1];
        const float  v1 = s_val[i + 1];
        const float4 h1 = *(const float4*)&h[(size_t)s_src[i + 1] * D_OUT + lane * 4];

        if (d0 != cur) {
            flush_acc(out, cur, lane, acc);
            acc = make_float4(0.f, 0.f, 0.f, 0.f);
            cur = d0;
        }
        acc.x = fmaf(v0, h0.x, acc.x);
        acc.y = fmaf(v0, h0.y, acc.y);
        acc.z = fmaf(v0, h0.z, acc.z);
        acc.w = fmaf(v0, h0.w, acc.w);

        d0 = d1; v0 = v1; h0 = h1;
    }
    // last edge
    if (d0 != cur) {
        flush_acc(out, cur, lane, acc);
        acc = make_float4(0.f, 0.f, 0.f, 0.f);
        cur = d0;
    }
    acc.x = fmaf(v0, h0.x, acc.x);
    acc.y = fmaf(v0, h0.y, acc.y);
    acc.z = fmaf(v0, h0.z, acc.z);
    acc.w = fmaf(v0, h0.w, acc.w);
    flush_acc(out, cur, lane, acc);
}

// ---------------------------------------------------------------------------
// Launch.  Inputs: x, edge_src, edge_dst, edge_vals, weight, bias
// ---------------------------------------------------------------------------
extern "C" void kernel_launch(void* const* d_in, const int* in_sizes, int n_in,
                              void* d_out, int out_size)
{
    const float* x        = (const float*)d_in[0];
    const int*   edge_src = (const int*)  d_in[1];
    const int*   edge_dst = (const int*)  d_in[2];
    const float* edge_val = (const float*)d_in[3];
    const float* weight   = (const float*)d_in[4];
    const float* bias     = (const float*)d_in[5];
    float*       out      = (float*)d_out;

    float* h;
    cudaGetSymbolAddress((void**)&h, g_h);

    gemm_kernel<<<(N_NODES + 63) / 64, 128>>>(x, weight, h);

    init_kernel<<<(N_NODES * D_OUT / 4 + 255) / 256, 256>>>(out, bias);

    scatter_kernel<<<(N_EDGES + EPB - 1) / EPB, 128>>>(
        edge_src, edge_dst, edge_val, h, out);
}